// round 12
// baseline (speedup 1.0000x reference)
#include <cuda_runtime.h>
#include <cuda_bf16.h>
#include <math.h>
#include <stdint.h>

#define B      4096
#define NN     2048
#define NIN    512
#define NOUT   256
#define NSTG   12
#define NTILES 228               // sum over stages of (8+2*st)
#define CHBYTES 40960            // per-chunk buffer: A_hi 16K | A_lo 16K | B_hi 4K | B_lo 4K
#define NTHR   512

// ---------------- static device scratch (no allocs) ----------------
__device__ __align__(16) unsigned char g_wtile[(size_t)NTILES * 32768]; // per chunk: A_hi 16K | A_lo 16K (SW128 images)
__device__ __align__(16) float         g_wdp[NSTG * 20480];             // diag W padded: [st][s*160 + g*20 + i]
__device__ __align__(16) unsigned char g_bact[(size_t)128 * 32 * 8192]; // per (cta,chunk): B_hi 4K | B_lo 4K (SW128 images)

// ---------------- smem layout (bytes) ----------------
#define OFF_WDP    122880        // after 3 x 40960 chunk buffers
#define OFF_ZS     204800        // 128*33*4 = 16896
#define SMEM_TOTAL 221696

__host__ __device__ __forceinline__ unsigned sw128(unsigned x) { return x ^ ((x >> 3) & 0x70); }

__device__ __forceinline__ uint32_t s2u(const void* p) { return (uint32_t)__cvta_generic_to_shared(p); }

__device__ __forceinline__ void cpa16(uint32_t dst, const void* src) {
    asm volatile("cp.async.cg.shared.global [%0], [%1], 16;" :: "r"(dst), "l"(src) : "memory");
}
#define CP_COMMIT()  asm volatile("cp.async.commit_group;" ::: "memory")
#define CP_WAIT2()   asm volatile("cp.async.wait_group 2;" ::: "memory")

__device__ __forceinline__ void ldsm4(uint32_t* r, uint32_t addr) {
    asm volatile("ldmatrix.sync.aligned.m8n8.x4.shared.b16 {%0,%1,%2,%3}, [%4];"
                 : "=r"(r[0]), "=r"(r[1]), "=r"(r[2]), "=r"(r[3]) : "r"(addr));
}
__device__ __forceinline__ void mma16816(float* d, const uint32_t* a, const uint32_t* b) {
    asm volatile("mma.sync.aligned.m16n8k16.row.col.f32.bf16.bf16.f32 "
                 "{%0,%1,%2,%3}, {%4,%5,%6,%7}, {%8,%9}, {%0,%1,%2,%3};"
                 : "+f"(d[0]), "+f"(d[1]), "+f"(d[2]), "+f"(d[3])
                 : "r"(a[0]), "r"(a[1]), "r"(a[2]), "r"(a[3]), "r"(b[0]), "r"(b[1]));
}
__device__ __forceinline__ uint32_t packhl(float v0, float v1, uint32_t& lp) {
    __nv_bfloat16 h0 = __float2bfloat16(v0), h1 = __float2bfloat16(v1);
    __nv_bfloat16 l0 = __float2bfloat16(v0 - __bfloat162float(h0));
    __nv_bfloat16 l1 = __float2bfloat16(v1 - __bfloat162float(h1));
    lp = ((uint32_t)__bfloat16_as_ushort(l1) << 16) | (uint32_t)__bfloat16_as_ushort(l0);
    return ((uint32_t)__bfloat16_as_ushort(h1) << 16) | (uint32_t)__bfloat16_as_ushort(h0);
}
__device__ __forceinline__ int stage_of(int g) {
    int s = 0;
    while (s + 1 < NSTG && (s + 1) * (s + 8) <= g) ++s;   // tb(s) = s*(s+7)
    return s;
}

// ---------------- prep kernels (deterministic, rerun every launch) ----------------
__global__ void prep_w(const float* __restrict__ W) {
    int tl = blockIdx.x;
    int st = stage_of(tl);
    int c = tl - st * (st + 7);
    unsigned char* dst = g_wtile + (size_t)tl * 32768;
    for (int e = threadIdx.x; e < 4096; e += 256) {
        int t = e >> 5, p = e & 31;
        const float* src = &W[(size_t)(st * 128 + t) * NN + c * 64 + 2 * p];
        uint32_t lp, hp = packhl(src[0], src[1], lp);
        unsigned off = sw128((unsigned)(t * 128 + 4 * p));
        *(uint32_t*)(dst + off)         = hp;
        *(uint32_t*)(dst + 16384 + off) = lp;
    }
}

__global__ void prep_wd(const float* __restrict__ W) {
    int e = blockIdx.x * 256 + threadIdx.x;            // 12*20480 entries
    if (e >= NSTG * 20480) return;
    int st = e / 20480, rem = e % 20480;
    int s = rem / 160, r2 = rem % 160;
    int g = r2 / 20, i = r2 % 20;
    float v = 0.f;
    if (i < 16) v = W[(size_t)(st * 128 + 8 * i + g) * NN + NIN + st * 128 + s];
    g_wdp[e] = v;   // zero above/on diagonal comes from the input mask itself
}

__global__ void init_kernel(const float* __restrict__ x) {
    int cta = blockIdx.x, ch = blockIdx.y;
    int p = threadIdx.x & 31, b0 = threadIdx.x >> 5;
    unsigned char* dst = g_bact + ((size_t)cta * 32 + ch) * 8192;
    #pragma unroll
    for (int j = 0; j < 4; ++j) {
        int b = b0 + 8 * j;
        const float* src = &x[(size_t)(cta * 32 + b) * NIN + ch * 64 + 2 * p];
        uint32_t lp, hp = packhl(src[0], src[1], lp);
        unsigned off = sw128((unsigned)(b * 128 + 4 * p));
        *(uint32_t*)(dst + off)        = hp;
        *(uint32_t*)(dst + 4096 + off) = lp;
    }
}

// ---------------- main kernel: 1 CTA = 32 batch rows, 16 warps, all 12 stages ----------------
__device__ __forceinline__ void issue_chunk(int g, int cta, uint32_t smem0, int tid) {
    int s = stage_of(g);
    int c = g - s * (s + 7);
    uint32_t dst = smem0 + (uint32_t)(g % 3) * CHBYTES;
    const unsigned char* srcA = g_wtile + (size_t)g * 32768;
    const unsigned char* srcB = g_bact + ((size_t)cta * 32 + c) * 8192;
    #pragma unroll
    for (int i = 0; i < 4; ++i) cpa16(dst + 16u * (tid + NTHR * i), srcA + 16 * (tid + NTHR * i));
    cpa16(dst + 32768u + 16u * tid, srcB + 16 * tid);
    if (c == 5) {   // diag W for stage s rides in this group (prev stage's WDP already consumed)
        const unsigned char* srcW = (const unsigned char*)(g_wdp + s * 20480);
        #pragma unroll
        for (int i = 0; i < 10; ++i) cpa16(smem0 + OFF_WDP + 16u * (tid + NTHR * i), srcW + 16 * (tid + NTHR * i));
    }
}

__global__ void __launch_bounds__(NTHR, 1)
net_kernel(const float* __restrict__ bias, float* __restrict__ out) {
    extern __shared__ char smem[];
    float* Zs   = (float*)(smem + OFF_ZS);
    float* WdpF = (float*)(smem + OFF_WDP);
    const int tid = threadIdx.x, wid = tid >> 5, lid = tid & 31;
    const int cta = blockIdx.x, bbase = cta * 32;
    const uint32_t smem0 = s2u(smem);
    const int wm = wid & 7;                  // node-strip (M) index
    const int kw = wid >> 3;                 // k-half: 0 -> ks 0,1 ; 1 -> ks 2,3
    const int nb = wm * 16;                  // node base of this warp's M-strip

    // prologue: chunks 0,1,2 (all x-data for stage 0)
    for (int g = 0; g < 3; ++g) { issue_chunk(g, cta, smem0, tid); CP_COMMIT(); }

    int gidx = 0;
    for (int st = 0; st < NSTG; ++st) {
        const int nch = 8 + 2 * st;

        float d[4][4];
        #pragma unroll
        for (int nt = 0; nt < 4; ++nt)
            #pragma unroll
            for (int q = 0; q < 4; ++q) d[nt][q] = 0.f;

        for (int ch = 0; ch < nch; ++ch, ++gidx) {
            CP_WAIT2();                       // chunk gidx complete (this thread)
            __syncthreads();                  // ... for all threads

            const uint32_t buf = smem0 + (uint32_t)(gidx % 3) * CHBYTES;
            #pragma unroll
            for (int kq = 0; kq < 2; ++kq) {
                const int ks = kw * 2 + kq;   // this warp's k16 sub-steps
                uint32_t ah[4], al[4], bh[8], bl[8];
                unsigned aoff = (unsigned)(nb + (lid & 15)) * 128 + ((lid >> 4) * 16 + ks * 32);
                ldsm4(ah, buf + sw128(aoff));
                ldsm4(al, buf + 16384 + sw128(aoff));
                unsigned nrow = (lid & 7) + ((lid >> 4) & 1) * 8;
                unsigned kb   = ((lid >> 3) & 1) * 16 + ks * 32;
                ldsm4(bh,     buf + 32768 + sw128(nrow * 128 + kb));
                ldsm4(bh + 4, buf + 32768 + sw128((nrow + 16) * 128 + kb));
                ldsm4(bl,     buf + 36864 + sw128(nrow * 128 + kb));
                ldsm4(bl + 4, buf + 36864 + sw128((nrow + 16) * 128 + kb));
                #pragma unroll
                for (int nt = 0; nt < 4; ++nt) {
                    mma16816(d[nt], ah, &bh[2 * nt]);   // Ah*Bh
                    mma16816(d[nt], ah, &bl[2 * nt]);   // Ah*Bl
                    mma16816(d[nt], al, &bh[2 * nt]);   // Al*Bh
                }
            }
            __syncthreads();                  // done reading buf before it is re-filled

            if (gidx + 3 < NTILES) issue_chunk(gidx + 3, cta, smem0, tid);
            CP_COMMIT();                      // one group per iteration (possibly empty)
        }

        // ---- epilogue: reduce the two k-halves; d-frags + bias -> Zs[node*33 + batch] ----
        {
            int m0 = nb + (lid >> 2), m1 = m0 + 8;
            if (kw == 0) {
                float bi0 = __ldg(&bias[st * 128 + m0]);
                float bi1 = __ldg(&bias[st * 128 + m1]);
                #pragma unroll
                for (int nt = 0; nt < 4; ++nt) {
                    int c = nt * 8 + 2 * (lid & 3);
                    Zs[m0 * 33 + c]     = d[nt][0] + bi0;
                    Zs[m0 * 33 + c + 1] = d[nt][1] + bi0;
                    Zs[m1 * 33 + c]     = d[nt][2] + bi1;
                    Zs[m1 * 33 + c + 1] = d[nt][3] + bi1;
                }
            }
            __syncthreads();
            if (kw == 1) {
                #pragma unroll
                for (int nt = 0; nt < 4; ++nt) {
                    int c = nt * 8 + 2 * (lid & 3);
                    Zs[m0 * 33 + c]     += d[nt][0];
                    Zs[m0 * 33 + c + 1] += d[nt][1];
                    Zs[m1 * 33 + c]     += d[nt][2];
                    Zs[m1 * 33 + c + 1] += d[nt][3];
                }
            }
        }
        __syncthreads();

        // ---- triangular recurrence (warps 0-7): 128 sequential sigmoid steps, guard-free ----
        if (wid < 8) {
            const int r = lid >> 3, g = lid & 7;
            const int bl2 = wid * 4 + r;
            float z[16];
            #pragma unroll
            for (int i = 0; i < 16; i++) z[i] = Zs[(8 * i + g) * 33 + bl2];

            #pragma unroll
            for (int s = 0; s < 128; ++s) {
                float zv = __shfl_sync(0xffffffffu, z[s >> 3], (r << 3) | (s & 7));
                float t5 = fminf(fmaxf(5.0f * zv, -60.0f), 60.0f);
                float o  = __fdividef(1.0f, 1.0f + __expf(-t5));
                if ((s & 7) == g) z[s >> 3] = o;
                const float4* w4 = (const float4*)&WdpF[s * 160 + g * 20];
                float4 w0 = w4[0], w1 = w4[1], w2 = w4[2], w3 = w4[3];
                z[0] += w0.x*o; z[1] += w0.y*o; z[2]  += w0.z*o; z[3]  += w0.w*o;
                z[4] += w1.x*o; z[5] += w1.y*o; z[6]  += w1.z*o; z[7]  += w1.w*o;
                z[8] += w2.x*o; z[9] += w2.y*o; z[10] += w2.z*o; z[11] += w2.w*o;
                z[12]+= w3.x*o; z[13]+= w3.y*o; z[14] += w3.z*o; z[15] += w3.w*o;
            }
            #pragma unroll
            for (int i = 0; i < 16; i++) Zs[(8 * i + g) * 33 + bl2] = z[i];   // now the o's
        }
        __syncthreads();

        // ---- writeback (warps 0-7): new activations as bf16 hi/lo images (+ f32 out for st>=10) ----
        if (wid < 8) {
            unsigned char* dst0 = g_bact + ((size_t)cta * 32 + 8 + 2 * st) * 8192;
            #pragma unroll
            for (int c = 0; c < 2; ++c) {
                unsigned char* dst = dst0 + c * 8192;
                #pragma unroll
                for (int jj = 0; jj < 4; ++jj) {
                    int b  = wid + 8 * jj;
                    int tl = c * 64 + 2 * lid;
                    float v0 = Zs[tl * 33 + b], v1 = Zs[(tl + 1) * 33 + b];
                    uint32_t lp, hp = packhl(v0, v1, lp);
                    unsigned off = sw128((unsigned)(b * 128 + 4 * lid));
                    *(uint32_t*)(dst + off)        = hp;
                    *(uint32_t*)(dst + 4096 + off) = lp;
                    if (st >= 10) {
                        int q = 128 * (st - 10) + tl;
                        *(float2*)&out[(size_t)(bbase + b) * NOUT + q] = make_float2(v0, v1);
                    }
                }
            }
        }
        __syncthreads();   // writeback visible (CTA scope) before any cp.async reads it
    }
}

extern "C" void kernel_launch(void* const* d_in, const int* in_sizes, int n_in,
                              void* d_out, int out_size) {
    const float* x = (const float*)d_in[0];   // [4096, 512]
    const float* W = (const float*)d_in[1];   // [1536, 2048]
    const float* b = (const float*)d_in[2];   // [1536]
    (void)in_sizes; (void)n_in; (void)out_size;

    cudaFuncSetAttribute(net_kernel, cudaFuncAttributeMaxDynamicSharedMemorySize, SMEM_TOTAL);

    prep_w<<<NTILES, 256>>>(W);
    prep_wd<<<(NSTG * 20480 + 255) / 256, 256>>>(W);
    init_kernel<<<dim3(128, 8), 256>>>(x);
    net_kernel<<<128, NTHR, SMEM_TOTAL>>>(b, (float*)d_out);
}